// round 1
// baseline (speedup 1.0000x reference)
#include <cuda_runtime.h>
#include <math.h>

#define BN   2
#define NPTS 2048
#define CCH  256
#define NH   4
#define HDIM 64
#define NL   4
#define BHN  (BN*NH)
#define EPSBN 1e-5f

// ---------------- scratch (device globals; no allocation allowed) -------------
__device__ float g_bufA[BN*CCH*NPTS];
__device__ float g_bufB[BN*CCH*NPTS];
__device__ float g_q  [BN*CCH*NPTS];
__device__ float g_k  [BN*CCH*NPTS];
__device__ float g_v  [BN*CCH*NPTS];
__device__ float g_d  [BN*CCH*NPTS];
__device__ float g_S  [(size_t)BHN*NPTS*NPTS];   // 134 MB attention scratch
__device__ float g_cs [BHN*NPTS];

// ---------------- transposes ----------------
// x[b][n][c] -> h[b][c][n]
__global__ void k_transpose_in(const float* __restrict__ x, float* __restrict__ h) {
    __shared__ float tile[32][33];
    int b = blockIdx.z;
    int n0 = blockIdx.x * 32, c0 = blockIdx.y * 32;
    int tx = threadIdx.x, ty = threadIdx.y;
    for (int i = ty; i < 32; i += 8)
        tile[i][tx] = x[(size_t)b*NPTS*CCH + (size_t)(n0+i)*CCH + c0 + tx];
    __syncthreads();
    for (int i = ty; i < 32; i += 8)
        h[(size_t)b*CCH*NPTS + (size_t)(c0+i)*NPTS + n0 + tx] = tile[tx][i];
}

// h[b][c][n] -> out[b][n][c]
__global__ void k_transpose_out(const float* __restrict__ h, float* __restrict__ out) {
    __shared__ float tile[32][33];
    int b = blockIdx.z;
    int c0 = blockIdx.x * 32, n0 = blockIdx.y * 32;
    int tx = threadIdx.x, ty = threadIdx.y;
    for (int i = ty; i < 32; i += 8)
        tile[i][tx] = h[(size_t)b*CCH*NPTS + (size_t)(c0+i)*NPTS + n0 + tx];
    __syncthreads();
    for (int i = ty; i < 32; i += 8)
        out[(size_t)b*NPTS*CCH + (size_t)(n0+i)*CCH + c0 + tx] = tile[tx][i];
}

// ---------------- full-channel GEMM: out[b][o][n] = act(alpha[o]*GEMM + beta[o]) ----
// W: [256][256], in: [b][256][2048]. gvec!=null -> BN fold (alpha=g*rsqrt(1+eps),
// beta=bvec*alpha+bevec); else beta=bvec (or 0).
__global__ void k_gemm_full(const float* __restrict__ W, const float* __restrict__ in,
                            float* __restrict__ out, const float* __restrict__ bvec,
                            const float* __restrict__ gvec, const float* __restrict__ bevec,
                            int relu) {
    __shared__ float As[32][65];   // [cc][oo]
    __shared__ float Bs[32][64];   // [cc][nn]
    int b  = blockIdx.z;
    int n0 = blockIdx.x * 64, o0 = blockIdx.y * 64;
    int t  = threadIdx.x;
    int tx = t & 15, ty = t >> 4;
    const float* inb = in + (size_t)b*CCH*NPTS;
    float acc[4][4] = {};
    for (int kc = 0; kc < CCH; kc += 32) {
        for (int r = t; r < 64*32; r += 256) {
            int oo = r >> 5, cc = r & 31;
            As[cc][oo] = W[(size_t)(o0+oo)*CCH + kc + cc];
        }
        for (int r = t; r < 32*64; r += 256) {
            int cc = r >> 6, nn = r & 63;
            Bs[cc][nn] = inb[(size_t)(kc+cc)*NPTS + n0 + nn];
        }
        __syncthreads();
        #pragma unroll
        for (int cc = 0; cc < 32; cc++) {
            float a[4], bb[4];
            #pragma unroll
            for (int i = 0; i < 4; i++) a[i]  = As[cc][ty*4 + i];
            #pragma unroll
            for (int j = 0; j < 4; j++) bb[j] = Bs[cc][tx*4 + j];
            #pragma unroll
            for (int i = 0; i < 4; i++)
                #pragma unroll
                for (int j = 0; j < 4; j++)
                    acc[i][j] = fmaf(a[i], bb[j], acc[i][j]);
        }
        __syncthreads();
    }
    float* outb = out + (size_t)b*CCH*NPTS;
    #pragma unroll
    for (int i = 0; i < 4; i++) {
        int o = o0 + ty*4 + i;
        float alpha = 1.f, beta = 0.f;
        if (gvec) { alpha = gvec[o] * rsqrtf(1.f + EPSBN); beta = bvec[o]*alpha + bevec[o]; }
        else if (bvec) beta = bvec[o];
        #pragma unroll
        for (int j = 0; j < 4; j++) {
            float vv = fmaf(acc[i][j], alpha, beta);
            if (relu) vv = fmaxf(vv, 0.f);
            outb[(size_t)o*NPTS + n0 + tx*4 + j] = vv;
        }
    }
}

// ---------------- per-head GEMM: out[bh][o][n] = ep(sum_c W[l,h,o,c] in[bh][c][n]) ----
// residual!=0: out[..] += relu(...). bng!=null: BN fold with bias=t_b, bnb.
__global__ void k_gemm_head(const float* __restrict__ Wbase, const float* __restrict__ in,
                            float* __restrict__ out, const float* __restrict__ bias,
                            const float* __restrict__ bng, const float* __restrict__ bnb,
                            int relu, int residual, int l) {
    __shared__ float As[64][65];   // [cc][oo]
    __shared__ float Bs[64][64];   // [cc][nn]
    int bh = blockIdx.y;
    int hh = bh & (NH - 1);
    int n0 = blockIdx.x * 64;
    const float* W   = Wbase + (size_t)(l*NH + hh) * HDIM * HDIM;
    const float* inb = in  + (size_t)bh * HDIM * NPTS;
    float*       outb= out + (size_t)bh * HDIM * NPTS;
    int t = threadIdx.x, tx = t & 15, ty = t >> 4;
    for (int r = t; r < 64*64; r += 256) {
        int oo = r >> 6, cc = r & 63;
        As[cc][oo] = W[r];                       // W[oo*64+cc], coalesced
    }
    for (int r = t; r < 64*64; r += 256) {
        int cc = r >> 6, nn = r & 63;
        Bs[cc][nn] = inb[(size_t)cc*NPTS + n0 + nn];
    }
    __syncthreads();
    float acc[4][4] = {};
    #pragma unroll
    for (int cc = 0; cc < 64; cc++) {
        float a[4], bb[4];
        #pragma unroll
        for (int i = 0; i < 4; i++) a[i]  = As[cc][ty*4 + i];
        #pragma unroll
        for (int j = 0; j < 4; j++) bb[j] = Bs[cc][tx*4 + j];
        #pragma unroll
        for (int i = 0; i < 4; i++)
            #pragma unroll
            for (int j = 0; j < 4; j++)
                acc[i][j] = fmaf(a[i], bb[j], acc[i][j]);
    }
    int vbase = (l*NH + hh) * HDIM;
    #pragma unroll
    for (int i = 0; i < 4; i++) {
        int o = ty*4 + i;
        float alpha = 1.f, beta = 0.f;
        if (bng) { alpha = bng[vbase+o] * rsqrtf(1.f + EPSBN); beta = bias[vbase+o]*alpha + bnb[vbase+o]; }
        else if (bias) beta = bias[vbase + o];
        #pragma unroll
        for (int j = 0; j < 4; j++) {
            float vv = fmaf(acc[i][j], alpha, beta);
            if (relu) vv = fmaxf(vv, 0.f);
            size_t oi = (size_t)o*NPTS + n0 + tx*4 + j;
            if (residual) outb[oi] += vv;
            else          outb[oi]  = vv;
        }
    }
}

// ---------------- attention scores: S[bh][n][m] = sum_o q[bh][o][n]*k[bh][o][m] ------
__global__ void k_scores(const float* __restrict__ q, const float* __restrict__ k,
                         float* __restrict__ S) {
    __shared__ float Qs[64][64];   // [o][nn]
    __shared__ float Ks[64][64];   // [o][mm]
    int bh = blockIdx.z;
    int n0 = blockIdx.y * 64, m0 = blockIdx.x * 64;
    const float* qb = q + (size_t)bh * HDIM * NPTS;
    const float* kb = k + (size_t)bh * HDIM * NPTS;
    int t = threadIdx.x, tx = t & 15, ty = t >> 4;
    for (int r = t; r < 4096; r += 256) {
        int o = r >> 6, nn = r & 63;
        Qs[o][nn] = qb[(size_t)o*NPTS + n0 + nn];
    }
    for (int r = t; r < 4096; r += 256) {
        int o = r >> 6, mm = r & 63;
        Ks[o][mm] = kb[(size_t)o*NPTS + m0 + mm];
    }
    __syncthreads();
    float acc[4][4] = {};
    #pragma unroll
    for (int o = 0; o < 64; o++) {
        float a[4], bb[4];
        #pragma unroll
        for (int i = 0; i < 4; i++) a[i]  = Qs[o][ty*4 + i];
        #pragma unroll
        for (int j = 0; j < 4; j++) bb[j] = Ks[o][tx*4 + j];
        #pragma unroll
        for (int i = 0; i < 4; i++)
            #pragma unroll
            for (int j = 0; j < 4; j++)
                acc[i][j] = fmaf(a[i], bb[j], acc[i][j]);
    }
    float* Sb = S + (size_t)bh * NPTS * NPTS;
    #pragma unroll
    for (int i = 0; i < 4; i++)
        #pragma unroll
        for (int j = 0; j < 4; j++)
            Sb[(size_t)(n0 + ty*4 + i)*NPTS + m0 + tx*4 + j] = acc[i][j];
}

// ---------------- row softmax (axis m), in place -------------------------------------
__global__ void k_softmax(float* __restrict__ S) {
    int bh = blockIdx.y;
    int n  = blockIdx.x;
    float* row = S + (size_t)bh*NPTS*NPTS + (size_t)n*NPTS;
    int t = threadIdx.x;
    __shared__ float red[256];
    float vals[8];
    float mx = -1e30f;
    #pragma unroll
    for (int i = 0; i < 8; i++) { vals[i] = row[t + i*256]; mx = fmaxf(mx, vals[i]); }
    red[t] = mx; __syncthreads();
    for (int s = 128; s > 0; s >>= 1) { if (t < s) red[t] = fmaxf(red[t], red[t+s]); __syncthreads(); }
    mx = red[0]; __syncthreads();
    float sum = 0.f;
    #pragma unroll
    for (int i = 0; i < 8; i++) { vals[i] = __expf(vals[i] - mx); sum += vals[i]; }
    red[t] = sum; __syncthreads();
    for (int s = 128; s > 0; s >>= 1) { if (t < s) red[t] += red[t+s]; __syncthreads(); }
    float inv = 1.f / red[0];
    #pragma unroll
    for (int i = 0; i < 8; i++) row[t + i*256] = vals[i] * inv;
}

// ---------------- column sums of P (over n), chunked with atomics --------------------
__global__ void k_zero_cs(float* __restrict__ cs) {
    cs[blockIdx.x * 256 + threadIdx.x] = 0.f;
}
__global__ void k_colsum(const float* __restrict__ S, float* __restrict__ cs) {
    int bh = blockIdx.y;
    int m  = blockIdx.x * 256 + threadIdx.x;
    int n0 = blockIdx.z * 64;
    const float* Sb = S + (size_t)bh * NPTS * NPTS;
    float acc = 0.f;
    #pragma unroll 8
    for (int n = n0; n < n0 + 64; n++) acc += Sb[(size_t)n*NPTS + m];
    atomicAdd(&cs[bh*NPTS + m], acc);
}

// ---------------- d = h - (xv @ P) / (1e-9 + colsum) ---------------------------------
__global__ void k_dcomp(const float* __restrict__ v, const float* __restrict__ S,
                        const float* __restrict__ cs, const float* __restrict__ h,
                        float* __restrict__ d) {
    __shared__ float Vs[32][65];   // [nn][cc]
    __shared__ float Ps[32][64];   // [nn][mm]
    int bh = blockIdx.y;
    int m0 = blockIdx.x * 64;
    const float* vb = v + (size_t)bh * HDIM * NPTS;
    const float* Sb = S + (size_t)bh * NPTS * NPTS;
    int t = threadIdx.x, tx = t & 15, ty = t >> 4;
    float acc[4][4] = {};
    for (int kc = 0; kc < NPTS; kc += 32) {
        for (int r = t; r < 64*32; r += 256) {
            int cc = r >> 5, nn = r & 31;
            Vs[nn][cc] = vb[(size_t)cc*NPTS + kc + nn];
        }
        for (int r = t; r < 32*64; r += 256) {
            int nn = r >> 6, mm = r & 63;
            Ps[nn][mm] = Sb[(size_t)(kc + nn)*NPTS + m0 + mm];
        }
        __syncthreads();
        #pragma unroll
        for (int nn = 0; nn < 32; nn++) {
            float a[4], bb[4];
            #pragma unroll
            for (int i = 0; i < 4; i++) a[i]  = Vs[nn][ty*4 + i];
            #pragma unroll
            for (int j = 0; j < 4; j++) bb[j] = Ps[nn][tx*4 + j];
            #pragma unroll
            for (int i = 0; i < 4; i++)
                #pragma unroll
                for (int j = 0; j < 4; j++)
                    acc[i][j] = fmaf(a[i], bb[j], acc[i][j]);
        }
        __syncthreads();
    }
    const float* hb = h + (size_t)bh * HDIM * NPTS;
    float*       db = d + (size_t)bh * HDIM * NPTS;
    #pragma unroll
    for (int i = 0; i < 4; i++) {
        int c = ty*4 + i;
        #pragma unroll
        for (int j = 0; j < 4; j++) {
            int m = m0 + tx*4 + j;
            float inv = 1.f / (1e-9f + cs[bh*NPTS + m]);
            size_t oi = (size_t)c*NPTS + m;
            db[oi] = hb[oi] - acc[i][j] * inv;
        }
    }
}

// ---------------- host orchestration -------------------------------------------------
extern "C" void kernel_launch(void* const* d_in, const int* in_sizes, int n_in,
                              void* d_out, int out_size) {
    const float* x      = (const float*)d_in[0];
    const float* in_w1  = (const float*)d_in[1];
    const float* in_b1  = (const float*)d_in[2];
    const float* in_g1  = (const float*)d_in[3];
    const float* in_be1 = (const float*)d_in[4];
    const float* in_w2  = (const float*)d_in[5];
    const float* in_b2  = (const float*)d_in[6];
    const float* in_g2  = (const float*)d_in[7];
    const float* in_be2 = (const float*)d_in[8];
    const float* q_w    = (const float*)d_in[9];
    const float* k_w    = (const float*)d_in[10];
    const float* v_w    = (const float*)d_in[11];
    const float* v_b    = (const float*)d_in[12];
    const float* t_w    = (const float*)d_in[13];
    const float* t_b    = (const float*)d_in[14];
    const float* bn_g   = (const float*)d_in[15];
    const float* bn_b   = (const float*)d_in[16];
    const float* proj_w = (const float*)d_in[17];
    const float* proj_b = (const float*)d_in[18];

    float *hA, *hB, *qb, *kb, *vb, *db, *Sb, *cs;
    cudaGetSymbolAddress((void**)&hA, g_bufA);
    cudaGetSymbolAddress((void**)&hB, g_bufB);
    cudaGetSymbolAddress((void**)&qb, g_q);
    cudaGetSymbolAddress((void**)&kb, g_k);
    cudaGetSymbolAddress((void**)&vb, g_v);
    cudaGetSymbolAddress((void**)&db, g_d);
    cudaGetSymbolAddress((void**)&Sb, g_S);
    cudaGetSymbolAddress((void**)&cs, g_cs);

    dim3 ttb(32, 8);
    k_transpose_in<<<dim3(NPTS/32, CCH/32, BN), ttb>>>(x, hA);

    k_gemm_full<<<dim3(NPTS/64, CCH/64, BN), 256>>>(in_w1, hA, hB, in_b1, in_g1, in_be1, 1);
    k_gemm_full<<<dim3(NPTS/64, CCH/64, BN), 256>>>(in_w2, hB, hA, in_b2, in_g2, in_be2, 1);

    float* h = hA;
    float* o = hB;
    for (int l = 0; l < NL; l++) {
        k_gemm_head<<<dim3(NPTS/64, BHN), 256>>>(q_w, h, qb, nullptr, nullptr, nullptr, 0, 0, l);
        k_gemm_head<<<dim3(NPTS/64, BHN), 256>>>(k_w, h, kb, nullptr, nullptr, nullptr, 0, 0, l);
        k_gemm_head<<<dim3(NPTS/64, BHN), 256>>>(v_w, h, vb, v_b,    nullptr, nullptr, 0, 0, l);

        k_scores <<<dim3(NPTS/64, NPTS/64, BHN), 256>>>(qb, kb, Sb);
        k_softmax<<<dim3(NPTS, BHN), 256>>>(Sb);
        k_zero_cs<<<BHN*NPTS/256, 256>>>(cs);
        k_colsum <<<dim3(NPTS/256, BHN, NPTS/64), 256>>>(Sb, cs);
        k_dcomp  <<<dim3(NPTS/64, BHN), 256>>>(vb, Sb, cs, h, db);

        k_gemm_head<<<dim3(NPTS/64, BHN), 256>>>(t_w, db, h, t_b, bn_g, bn_b, 1, 1, l);
        k_gemm_full<<<dim3(NPTS/64, CCH/64, BN), 256>>>(proj_w + (size_t)l*CCH*CCH, h, o,
                                                        proj_b + (size_t)l*CCH,
                                                        nullptr, nullptr, 0);
        float* tmp = h; h = o; o = tmp;
    }

    k_transpose_out<<<dim3(CCH/32, NPTS/32, BN), ttb>>>(h, (float*)d_out);
}